// round 8
// baseline (speedup 1.0000x reference)
#include <cuda_runtime.h>
#include <cuda_fp16.h>
#include <cstdint>

// ============================================================================
// LSTMCell on sm_100 (baseline PTX). mma.sync.m16n8k16 f16/f32.
// R7 -> R8: issue-bound fix. All ldmatrix/cp.async addressing strength-reduced
// out of the mainloop:
//   swz(r,c16) = (r*128 + ((r&7)<<4)) ^ (c16<<4)  -> per-warp base regs,
//   per-ldsm cost = 1 LOP3-with-immediate. cp.async src/dst use precomputed
//   per-thread bases + compile-time immediates.
// ============================================================================

#define BATCH 4096
#define KTOT  2048
#define BM 128
#define BN 128
#define BK 64
#define STAGES 2
#define A_STAGE_BYTES 16384               // 128 rows x 64 halfs (128B rows)
#define STAGE_BYTES   32768

__device__ __align__(16) __half g_Apack[(size_t)BATCH * KTOT];  // 16 MB
__device__ __align__(16) __half g_Bpack[(size_t)4096 * KTOT];   // 16 MB

// ---------------------------------------------------------------- helpers
__device__ __forceinline__ uint32_t smem_u32(const void* p) {
    uint32_t a;
    asm("{ .reg .u64 t; cvta.to.shared.u64 t, %1; cvt.u32.u64 %0, t; }" : "=r"(a) : "l"(p));
    return a;
}
__device__ __forceinline__ void cpasync16(uint32_t dst, const void* src) {
    asm volatile("cp.async.cg.shared.global [%0], [%1], 16;" :: "r"(dst), "l"(src));
}
__device__ __forceinline__ void cp_commit() { asm volatile("cp.async.commit_group;" ::: "memory"); }
template <int N>
__device__ __forceinline__ void cp_wait() { asm volatile("cp.async.wait_group %0;" :: "n"(N) : "memory"); }

// canonical swizzle (used by pack-side reasoning and loader bases):
// swz(r,c16) = r*128 + (((c16 ^ (r&7)) & 7) << 4)
//            = (r*128 + ((r&7)<<4)) ^ ((c16&7)<<4)     [bit fields disjoint]
__device__ __forceinline__ uint32_t swz(uint32_t r, uint32_t c16) {
    return r * 128u + (((c16 ^ (r & 7u)) & 7u) << 4);
}

__device__ __forceinline__ void ldsm_x4(uint32_t* r, uint32_t addr) {
    asm volatile("ldmatrix.sync.aligned.m8n8.x4.shared.b16 {%0,%1,%2,%3}, [%4];"
                 : "=r"(r[0]), "=r"(r[1]), "=r"(r[2]), "=r"(r[3]) : "r"(addr));
}
__device__ __forceinline__ void mma16816(float* c, const uint32_t* a, uint32_t b0, uint32_t b1) {
    asm volatile(
        "mma.sync.aligned.m16n8k16.row.col.f32.f16.f16.f32 "
        "{%0,%1,%2,%3}, {%4,%5,%6,%7}, {%8,%9}, {%0,%1,%2,%3};"
        : "+f"(c[0]), "+f"(c[1]), "+f"(c[2]), "+f"(c[3])
        : "r"(a[0]), "r"(a[1]), "r"(a[2]), "r"(a[3]), "r"(b0), "r"(b1));
}

__device__ __forceinline__ float sigm_f(float x) { return __fdividef(1.0f, 1.0f + __expf(-x)); }
__device__ __forceinline__ float tanh_f(float x) { return __fdividef(2.0f, 1.0f + __expf(-2.0f * x)) - 1.0f; }

// ---------------------------------------------------------------- merged pack
__global__ void __launch_bounds__(256) pack_all(const float* __restrict__ x,
                                                const float* __restrict__ h,
                                                const float* __restrict__ W,
                                                const float* __restrict__ V) {
    if (blockIdx.x < 8192) {
        size_t t = (size_t)blockIdx.x * 256 + threadIdx.x;
        size_t base = t * 4;
        int m = (int)(base >> 11);
        int k = (int)(base & 2047);
        const float* src = (k < 1024) ? (x + (size_t)m * 1024 + k)
                                      : (h + (size_t)m * 1024 + (k - 1024));
        float4 v = *reinterpret_cast<const float4*>(src);
        __half2 lo = __floats2half2_rn(v.x, v.y);
        __half2 hi = __floats2half2_rn(v.z, v.w);
        uint2 pk = make_uint2(*reinterpret_cast<uint32_t*>(&lo), *reinterpret_cast<uint32_t*>(&hi));
        *reinterpret_cast<uint2*>(&g_Apack[base]) = pk;
    } else {
        __shared__ float buf[32][33];
        const int idx0 = (int)blockIdx.x - 8192;
        const int nblk = idx0 & 127;   // orig n / 32
        const int kblk = idx0 >> 7;    // k / 32
        const int n0 = nblk * 32, k0 = kblk * 32;
        const float* src = (k0 < 1024) ? (W + (size_t)k0 * 4096 + n0)
                                       : (V + (size_t)(k0 - 1024) * 4096 + n0);
        for (int idx = threadIdx.x; idx < 1024; idx += 256) {
            int kl = idx >> 5, nl = idx & 31;
            buf[kl][nl] = src[(size_t)kl * 4096 + nl];
        }
        __syncthreads();
        for (int idx = threadIdx.x; idx < 512; idx += 256) {
            int nl = idx >> 4;
            int kp = (idx & 15) * 2;
            int norig = n0 + nl;
            int g = norig >> 10;
            int rem = norig & 1023;
            int np = ((rem >> 5) << 7) + (((rem >> 3) & 3) << 5) + (g << 3) + (rem & 7);
            __half2 hv = __floats2half2_rn(buf[kp][nl], buf[kp + 1][nl]);
            *reinterpret_cast<uint32_t*>(&g_Bpack[(size_t)np * KTOT + k0 + kp]) =
                *reinterpret_cast<uint32_t*>(&hv);
        }
    }
}

// ---------------------------------------------------------------- main GEMM + epilogue
// grid (32 j-blocks, 32 m-blocks), 128 threads = 4 warps (wm x wn = 2x2),
// warp tile 64x64 (4 m16 x 8 n8; nt = 4*jpair + gate). 2-stage pipeline, 3 CTAs/SM.
__global__ void __launch_bounds__(128, 3) lstm_main(const float* __restrict__ c_in,
                                                    const float* __restrict__ bias,
                                                    float* __restrict__ out) {
    extern __shared__ __align__(128) unsigned char smem[];
    const uint32_t sb = smem_u32(smem);
    const int tid  = threadIdx.x;
    const int lane = tid & 31;
    const int warp = tid >> 5;
    const int wm = warp >> 1;
    const int wn = warp & 1;
    const int bx = blockIdx.x;
    const int by = blockIdx.y;

    // ---- per-thread cp.async bases (loop-invariant)
    const uint32_t lr  = (uint32_t)(tid >> 3);       // 0..15: base row
    const uint32_t lc  = (uint32_t)(tid & 7);        // 16B chunk
    const __half* srcA = g_Apack + (size_t)by * BM * KTOT + (size_t)lr * KTOT + lc * 8;
    const __half* srcB = g_Bpack + (size_t)bx * BN * KTOT + (size_t)lr * KTOT + lc * 8;
    const uint32_t dstA = sb + swz(lr, lc);
    const uint32_t dstB = dstA + A_STAGE_BYTES;
    // rows advance by 16 per i-step: swz(r+16,c) = swz(r,c) + 2048 (r&7 invariant)

    auto load_stage = [&](int it) {
        const uint32_t so = (uint32_t)(it & 1) * STAGE_BYTES;
        const __half* sa = srcA + it * BK;
        const __half* sbp = srcB + it * BK;
#pragma unroll
        for (int i = 0; i < 8; i++) {
            cpasync16(dstA + so + i * 2048u, sa + (size_t)i * 16 * KTOT);
            cpasync16(dstB + so + i * 2048u, sbp + (size_t)i * 16 * KTOT);
        }
        cp_commit();
    };

    // ---- per-warp ldmatrix base addresses (loop-invariant; csel folded in)
    const uint32_t rlo  = (uint32_t)(lane & 15);
    const uint32_t csel = (uint32_t)(lane >> 4);
    uint32_t pA[4], pB[4];
#pragma unroll
    for (int mt = 0; mt < 4; ++mt) {
        uint32_t rowa = (uint32_t)(wm * 64 + mt * 16) + rlo;
        pA[mt] = sb + rowa * 128u + ((((rowa & 7u) ^ csel) & 7u) << 4);
        uint32_t rowb = (uint32_t)(wn * 64 + mt * 16) + rlo;
        pB[mt] = sb + A_STAGE_BYTES + rowb * 128u + ((((rowb & 7u) ^ csel) & 7u) << 4);
    }

    float acc[4][8][4];
#pragma unroll
    for (int i = 0; i < 4; i++)
#pragma unroll
        for (int j = 0; j < 8; j++)
#pragma unroll
            for (int q = 0; q < 4; q++) acc[i][j][q] = 0.0f;

    load_stage(0);

    const int NIT = KTOT / BK;  // 32
    for (int it = 0; it < NIT; ++it) {
        cp_wait<0>();
        __syncthreads();
        if (it + 1 < NIT) load_stage(it + 1);

        const uint32_t so = (uint32_t)(it & 1) * STAGE_BYTES;
        uint32_t qA[4], qB[4];
#pragma unroll
        for (int mt = 0; mt < 4; ++mt) { qA[mt] = pA[mt] + so; qB[mt] = pB[mt] + so; }

#pragma unroll
        for (int k16 = 0; k16 < 4; ++k16) {
            const uint32_t kx = (uint32_t)(k16 << 5);   // XOR immediate (bits 5-6)
            uint32_t a[4][4];
#pragma unroll
            for (int mt = 0; mt < 4; ++mt) ldsm_x4(a[mt], qA[mt] ^ kx);
#pragma unroll
            for (int gp = 0; gp < 4; ++gp) {
                uint32_t r4[4];
                ldsm_x4(r4, qB[gp] ^ kx);
#pragma unroll
                for (int mt = 0; mt < 4; ++mt) {
                    mma16816(acc[mt][2 * gp + 0], a[mt], r4[0], r4[2]);
                    mma16816(acc[mt][2 * gp + 1], a[mt], r4[1], r4[3]);
                }
            }
        }
    }

    // ---- epilogue (in-register: nt = 4*jpair + gate)
#pragma unroll
    for (int jp = 0; jp < 2; ++jp) {
        const int jg = bx * 32 + (wn * 2 + jp) * 8 + 2 * (lane & 3);
        float bi[4][2];
#pragma unroll
        for (int g = 0; g < 4; ++g) {
            bi[g][0] = bias[g * 1024 + jg];
            bi[g][1] = bias[g * 1024 + jg + 1];
        }
#pragma unroll
        for (int mt = 0; mt < 4; ++mt) {
#pragma unroll
            for (int hr = 0; hr < 2; ++hr) {
                int m = by * 128 + wm * 64 + mt * 16 + (lane >> 2) + hr * 8;
                const float2 cv = *reinterpret_cast<const float2*>(c_in + (size_t)m * 1024 + jg);
                float hv[2], co[2];
#pragma unroll
                for (int q = 0; q < 2; ++q) {
                    float ai = acc[mt][jp * 4 + 0][hr * 2 + q] + bi[0][q];
                    float af = acc[mt][jp * 4 + 1][hr * 2 + q] + bi[1][q];
                    float ao = acc[mt][jp * 4 + 2][hr * 2 + q] + bi[2][q];
                    float ag = acc[mt][jp * 4 + 3][hr * 2 + q] + bi[3][q];
                    float iv = sigm_f(ai);
                    float fv = sigm_f(af);
                    float ov = sigm_f(ao);
                    float gv = tanh_f(ag);
                    float cc = (q == 0) ? cv.x : cv.y;
                    float c2 = fmaf(iv, gv, fv * cc);
                    co[q] = c2;
                    hv[q] = ov * tanh_f(c2);
                }
                *reinterpret_cast<float2*>(out + (size_t)m * 1024 + jg) = make_float2(hv[0], hv[1]);
                *reinterpret_cast<float2*>(out + (size_t)BATCH * 1024 + (size_t)m * 1024 + jg) =
                    make_float2(co[0], co[1]);
            }
        }
    }
}

// ---------------------------------------------------------------- launch
extern "C" void kernel_launch(void* const* d_in, const int* in_sizes, int n_in,
                              void* d_out, int out_size) {
    (void)in_sizes; (void)n_in; (void)out_size;
    const float* x = (const float*)d_in[0];
    const float* h = (const float*)d_in[1];
    const float* c = (const float*)d_in[2];
    const float* W = (const float*)d_in[3];
    const float* V = (const float*)d_in[4];
    const float* b = (const float*)d_in[5];
    float* out = (float*)d_out;

    cudaFuncSetAttribute(lstm_main, cudaFuncAttributeMaxDynamicSharedMemorySize,
                         STAGES * STAGE_BYTES);

    pack_all<<<16384, 256>>>(x, h, W, V);
    lstm_main<<<dim3(32, 32), 128, STAGES * STAGE_BYTES>>>(c, b, out);
}

// round 9
// speedup vs baseline: 1.1213x; 1.1213x over previous
#include <cuda_runtime.h>
#include <cuda_fp16.h>
#include <cstdint>

// ============================================================================
// LSTMCell on sm_100 (baseline PTX). mma.sync.m16n8k16 f16/f32.
// R8 -> R9: LSU-relief fix. Cycle model showed LSU (LDSM 512 + LDGSTS 512 cyc)
// == tensor (1024 cyc) per CTA-iter -> mutual interference caps tensor at 58%.
// Replace per-thread cp.async with TMA bulk copies (cp.async.bulk + mbarrier):
// operands repacked as contiguous pre-swizzled 16KB blocks; 2 bulk ops/stage
// issued by one thread. LSU load halves; tensor should become sole binder.
// ============================================================================

#define BATCH 4096
#define KTOT  2048
#define BM 128
#define BN 128
#define BK 64
#define NT_K 32                    // 2048/64 k-chunks
#define TILE_BYTES 16384           // 128 x 64 halfs, swizzled block
#define STAGE_BYTES 32768          // A block + B block
#define SMEM_MAIN  (2 * STAGE_BYTES)
#define SMEM_TOTAL (SMEM_MAIN + 128)   // + mbarriers

__device__ __align__(1024) unsigned char g_Apack[(size_t)32 * NT_K * TILE_BYTES];  // 16 MB
__device__ __align__(1024) unsigned char g_Bpack[(size_t)32 * NT_K * TILE_BYTES];  // 16 MB

// ---------------------------------------------------------------- helpers
__device__ __forceinline__ uint32_t smem_u32(const void* p) {
    uint32_t a;
    asm("{ .reg .u64 t; cvta.to.shared.u64 t, %1; cvt.u32.u64 %0, t; }" : "=r"(a) : "l"(p));
    return a;
}
#define MBARRIER_INIT(addr, cnt) \
    asm volatile("mbarrier.init.shared.b64 [%0], %1;" :: "r"((uint32_t)(addr)), "r"((uint32_t)(cnt)) : "memory")
#define MBARRIER_EXPECT_TX(addr, bytes) \
    asm volatile("mbarrier.arrive.expect_tx.shared.b64 _, [%0], %1;" :: "r"((uint32_t)(addr)), "r"((uint32_t)(bytes)) : "memory")

__device__ __forceinline__ void mbar_wait(uint32_t mbar, uint32_t phase) {
    asm volatile(
        "{\n\t"
        ".reg .pred P;\n\t"
        "LAB_WAIT%=:\n\t"
        "mbarrier.try_wait.parity.acquire.cta.shared::cta.b64 P, [%0], %1, 0x989680;\n\t"
        "@!P bra LAB_WAIT%=;\n\t"
        "}"
        :: "r"(mbar), "r"(phase) : "memory");
}
__device__ __forceinline__ void bulk_g2s(uint32_t dst, const void* src, uint32_t bytes, uint32_t mbar) {
    asm volatile(
        "cp.async.bulk.shared::cluster.global.mbarrier::complete_tx::bytes [%0], [%1], %2, [%3];"
        :: "r"(dst), "l"(src), "r"(bytes), "r"(mbar) : "memory");
}

// block-internal swizzle: rows of 128B (64 halfs), 16B chunk c16 XOR row.
// swz(r,c16) = (r*128 + ((r&7)<<4)) ^ ((c16&7)<<4)
__device__ __forceinline__ uint32_t swz(uint32_t r, uint32_t c16) {
    return r * 128u + (((c16 ^ (r & 7u)) & 7u) << 4);
}

__device__ __forceinline__ void ldsm_x4(uint32_t* r, uint32_t addr) {
    asm volatile("ldmatrix.sync.aligned.m8n8.x4.shared.b16 {%0,%1,%2,%3}, [%4];"
                 : "=r"(r[0]), "=r"(r[1]), "=r"(r[2]), "=r"(r[3]) : "r"(addr));
}
__device__ __forceinline__ void mma16816(float* c, const uint32_t* a, uint32_t b0, uint32_t b1) {
    asm volatile(
        "mma.sync.aligned.m16n8k16.row.col.f32.f16.f16.f32 "
        "{%0,%1,%2,%3}, {%4,%5,%6,%7}, {%8,%9}, {%0,%1,%2,%3};"
        : "+f"(c[0]), "+f"(c[1]), "+f"(c[2]), "+f"(c[3])
        : "r"(a[0]), "r"(a[1]), "r"(a[2]), "r"(a[3]), "r"(b0), "r"(b1));
}

__device__ __forceinline__ float sigm_f(float x) { return __fdividef(1.0f, 1.0f + __expf(-x)); }
__device__ __forceinline__ float tanh_f(float x) { return __fdividef(2.0f, 1.0f + __expf(-2.0f * x)) - 1.0f; }

// ---------------------------------------------------------------- merged pack
// blocks [0,1024): pack_A — block (mt=blk>>5, kc=blk&31): swizzled 128x64 fp16
//   from [x|h] rows mt*128.., cols kc*64.. (k<1024 -> x, else h)
// blocks [1024,9216): pack_B — gate-permuted transpose of [W;V] into swizzled
//   blocks (nt, kc):  n' = 128*(j/32) + 32*((j/8)&3) + 8*g + (j&7)
__global__ void __launch_bounds__(256) pack_all(const float* __restrict__ x,
                                                const float* __restrict__ h,
                                                const float* __restrict__ W,
                                                const float* __restrict__ V) {
    if (blockIdx.x < 1024) {
        const int mt = (int)blockIdx.x >> 5;
        const int kc = (int)blockIdx.x & 31;
        unsigned char* dst = g_Apack + ((size_t)blockIdx.x << 14);
        const int m0 = mt * 128, k0 = kc * 64;
        const float* srcb = (k0 < 1024) ? (x + (size_t)m0 * 1024 + k0)
                                        : (h + (size_t)m0 * 1024 + (k0 - 1024));
#pragma unroll
        for (int i = 0; i < 4; i++) {
            int idx = (int)threadIdx.x + i * 256;    // 0..1023 16B chunks
            uint32_t r = (uint32_t)(idx >> 3);
            uint32_t c16 = (uint32_t)(idx & 7);
            const float* s = srcb + (size_t)r * 1024 + c16 * 8;
            float4 v0 = *reinterpret_cast<const float4*>(s);
            float4 v1 = *reinterpret_cast<const float4*>(s + 4);
            __half2 h0 = __floats2half2_rn(v0.x, v0.y);
            __half2 h1 = __floats2half2_rn(v0.z, v0.w);
            __half2 h2 = __floats2half2_rn(v1.x, v1.y);
            __half2 h3 = __floats2half2_rn(v1.z, v1.w);
            uint4 pk = make_uint4(*reinterpret_cast<uint32_t*>(&h0), *reinterpret_cast<uint32_t*>(&h1),
                                  *reinterpret_cast<uint32_t*>(&h2), *reinterpret_cast<uint32_t*>(&h3));
            *reinterpret_cast<uint4*>(dst + swz(r, c16)) = pk;
        }
    } else {
        __shared__ float buf[32][33];
        const int idx0 = (int)blockIdx.x - 1024;
        const int nblk = idx0 & 127;   // orig n / 32
        const int kblk = idx0 >> 7;    // k / 32
        const int n0 = nblk * 32, k0 = kblk * 32;
        const float* src = (k0 < 1024) ? (W + (size_t)k0 * 4096 + n0)
                                       : (V + (size_t)(k0 - 1024) * 4096 + n0);
        for (int idx = threadIdx.x; idx < 1024; idx += 256) {
            int kl = idx >> 5, nl = idx & 31;
            buf[kl][nl] = src[(size_t)kl * 4096 + nl];
        }
        __syncthreads();
        const int kchunk = kblk >> 1;             // 64-wide chunk index
        const int kbase = (kblk & 1) * 32;        // offset within chunk
        for (int idx = threadIdx.x; idx < 512; idx += 256) {
            int nl = idx >> 4;
            int kp = (idx & 15) * 2;
            int norig = n0 + nl;
            int g = norig >> 10;
            int rem = norig & 1023;
            int np = ((rem >> 5) << 7) + (((rem >> 3) & 3) << 5) + (g << 3) + (rem & 7);
            int nt = np >> 7;
            uint32_t r = (uint32_t)(np & 127);
            uint32_t kl = (uint32_t)(kbase + kp);
            __half2 hv = __floats2half2_rn(buf[kp][nl], buf[kp + 1][nl]);
            unsigned char* dst = g_Bpack + (((size_t)nt * NT_K + kchunk) << 14);
            *reinterpret_cast<uint32_t*>(dst + swz(r, kl >> 3) + (kl & 7) * 2) =
                *reinterpret_cast<uint32_t*>(&hv);
        }
    }
}

// ---------------------------------------------------------------- main GEMM + epilogue
// grid (32 j-blocks, 32 m-blocks), 128 threads = 4 warps (wm x wn = 2x2),
// warp tile 64x64. 2-stage TMA-bulk pipeline (mbarrier), 3 CTAs/SM.
__global__ void __launch_bounds__(128, 3) lstm_main(const float* __restrict__ c_in,
                                                    const float* __restrict__ bias,
                                                    float* __restrict__ out) {
    extern __shared__ __align__(1024) unsigned char smem[];
    const uint32_t sb = smem_u32(smem);
    const int tid  = threadIdx.x;
    const int lane = tid & 31;
    const int warp = tid >> 5;
    const int wm = warp >> 1;
    const int wn = warp & 1;
    const int bx = blockIdx.x;
    const int by = blockIdx.y;

    const uint32_t BAR = sb + SMEM_MAIN;   // full[0], full[1]
    if (tid == 0) {
        MBARRIER_INIT(BAR, 1);
        MBARRIER_INIT(BAR + 8, 1);
    }
    __syncthreads();

    const unsigned char* Ab = g_Apack + ((size_t)by * NT_K << 14);
    const unsigned char* Bb = g_Bpack + ((size_t)bx * NT_K << 14);

    auto issue = [&](int it) {
        const uint32_t s2 = (uint32_t)(it & 1);
        const uint32_t bar = BAR + s2 * 8;
        const uint32_t dst = sb + s2 * STAGE_BYTES;
        MBARRIER_EXPECT_TX(bar, STAGE_BYTES);
        bulk_g2s(dst, Ab + ((size_t)it << 14), TILE_BYTES, bar);
        bulk_g2s(dst + TILE_BYTES, Bb + ((size_t)it << 14), TILE_BYTES, bar);
    };

    if (tid == 0) issue(0);

    // per-warp ldmatrix bases (csel folded); per-ldsm cost = 1 XOR
    const uint32_t rlo  = (uint32_t)(lane & 15);
    const uint32_t csel = (uint32_t)(lane >> 4);
    uint32_t pA[4], pB[4];
#pragma unroll
    for (int mt = 0; mt < 4; ++mt) {
        uint32_t rowa = (uint32_t)(wm * 64 + mt * 16) + rlo;
        pA[mt] = sb + rowa * 128u + ((((rowa & 7u) ^ csel) & 7u) << 4);
        uint32_t rowb = (uint32_t)(wn * 64 + mt * 16) + rlo;
        pB[mt] = sb + TILE_BYTES + rowb * 128u + ((((rowb & 7u) ^ csel) & 7u) << 4);
    }

    float acc[4][8][4];
#pragma unroll
    for (int i = 0; i < 4; i++)
#pragma unroll
        for (int j = 0; j < 8; j++)
#pragma unroll
            for (int q = 0; q < 4; q++) acc[i][j][q] = 0.0f;

    const int NIT = NT_K;  // 32
    for (int it = 0; it < NIT; ++it) {
        const uint32_t s = (uint32_t)(it & 1);
        mbar_wait(BAR + s * 8, (uint32_t)((it >> 1) & 1));
        __syncthreads();                       // all warps done with other buffer
        if (tid == 0 && it + 1 < NIT) issue(it + 1);

        const uint32_t so = s * STAGE_BYTES;
        uint32_t qA[4], qB[4];
#pragma unroll
        for (int mt = 0; mt < 4; ++mt) { qA[mt] = pA[mt] + so; qB[mt] = pB[mt] + so; }

#pragma unroll
        for (int k16 = 0; k16 < 4; ++k16) {
            const uint32_t kx = (uint32_t)(k16 << 5);
            uint32_t a[4][4];
#pragma unroll
            for (int mt = 0; mt < 4; ++mt) ldsm_x4(a[mt], qA[mt] ^ kx);
#pragma unroll
            for (int gp = 0; gp < 4; ++gp) {
                uint32_t r4[4];
                ldsm_x4(r4, qB[gp] ^ kx);
#pragma unroll
                for (int mt = 0; mt < 4; ++mt) {
                    mma16816(acc[mt][2 * gp + 0], a[mt], r4[0], r4[2]);
                    mma16816(acc[mt][2 * gp + 1], a[mt], r4[1], r4[3]);
                }
            }
        }
    }

    // ---- epilogue (in-register: nt = 4*jpair + gate)
#pragma unroll
    for (int jp = 0; jp < 2; ++jp) {
        const int jg = bx * 32 + (wn * 2 + jp) * 8 + 2 * (lane & 3);
        float bi[4][2];
#pragma unroll
        for (int g = 0; g < 4; ++g) {
            bi[g][0] = bias[g * 1024 + jg];
            bi[g][1] = bias[g * 1024 + jg + 1];
        }
#pragma unroll
        for (int mt = 0; mt < 4; ++mt) {
#pragma unroll
            for (int hr = 0; hr < 2; ++hr) {
                int m = by * 128 + wm * 64 + mt * 16 + (lane >> 2) + hr * 8;
                const float2 cv = *reinterpret_cast<const float2*>(c_in + (size_t)m * 1024 + jg);
                float hv[2], co[2];
#pragma unroll
                for (int q = 0; q < 2; ++q) {
                    float ai = acc[mt][jp * 4 + 0][hr * 2 + q] + bi[0][q];
                    float af = acc[mt][jp * 4 + 1][hr * 2 + q] + bi[1][q];
                    float ao = acc[mt][jp * 4 + 2][hr * 2 + q] + bi[2][q];
                    float ag = acc[mt][jp * 4 + 3][hr * 2 + q] + bi[3][q];
                    float iv = sigm_f(ai);
                    float fv = sigm_f(af);
                    float ov = sigm_f(ao);
                    float gv = tanh_f(ag);
                    float cc = (q == 0) ? cv.x : cv.y;
                    float c2 = fmaf(iv, gv, fv * cc);
                    co[q] = c2;
                    hv[q] = ov * tanh_f(c2);
                }
                *reinterpret_cast<float2*>(out + (size_t)m * 1024 + jg) = make_float2(hv[0], hv[1]);
                *reinterpret_cast<float2*>(out + (size_t)BATCH * 1024 + (size_t)m * 1024 + jg) =
                    make_float2(co[0], co[1]);
            }
        }
    }
}

// ---------------------------------------------------------------- launch
extern "C" void kernel_launch(void* const* d_in, const int* in_sizes, int n_in,
                              void* d_out, int out_size) {
    (void)in_sizes; (void)n_in; (void)out_size;
    const float* x = (const float*)d_in[0];
    const float* h = (const float*)d_in[1];
    const float* c = (const float*)d_in[2];
    const float* W = (const float*)d_in[3];
    const float* V = (const float*)d_in[4];
    const float* b = (const float*)d_in[5];
    float* out = (float*)d_out;

    cudaFuncSetAttribute(lstm_main, cudaFuncAttributeMaxDynamicSharedMemorySize, SMEM_TOTAL);

    pack_all<<<9216, 256>>>(x, h, W, V);
    lstm_main<<<dim3(32, 32), 128, SMEM_TOTAL>>>(c, b, out);
}

// round 10
// speedup vs baseline: 1.1248x; 1.0031x over previous
#include <cuda_runtime.h>
#include <cuda_fp16.h>
#include <cstdint>

// ============================================================================
// LSTMCell on sm_100 (baseline PTX). mma.sync.m16n8k16 f16/f32.
// R9 -> R10: register-pressure + prefetch-depth fix.
//  - warp tile 64x64 -> 64x32 (8 warps/CTA, 256 thr): acc 128 -> 64 floats,
//    regs ~168 (spill-suspect) -> ~110, 2 CTAs/SM = 16 warps/SM.
//  - TMA pipeline 2 -> 3 stages, prefetch depth 2 (96KB smem/CTA).
// Packing (pre-swizzled 16KB blocks) unchanged from R9.
// ============================================================================

#define BATCH 4096
#define KTOT  2048
#define BM 128
#define BN 128
#define BK 64
#define NT_K 32                    // 2048/64 k-chunks
#define TILE_BYTES 16384           // 128 x 64 halfs, swizzled block
#define STAGE_BYTES 32768          // A block + B block
#define NSTAGE 3
#define SMEM_MAIN  (NSTAGE * STAGE_BYTES)
#define SMEM_TOTAL (SMEM_MAIN + 128)   // + mbarriers

__device__ __align__(1024) unsigned char g_Apack[(size_t)32 * NT_K * TILE_BYTES];  // 16 MB
__device__ __align__(1024) unsigned char g_Bpack[(size_t)32 * NT_K * TILE_BYTES];  // 16 MB

// ---------------------------------------------------------------- helpers
__device__ __forceinline__ uint32_t smem_u32(const void* p) {
    uint32_t a;
    asm("{ .reg .u64 t; cvta.to.shared.u64 t, %1; cvt.u32.u64 %0, t; }" : "=r"(a) : "l"(p));
    return a;
}
#define MBARRIER_INIT(addr, cnt) \
    asm volatile("mbarrier.init.shared.b64 [%0], %1;" :: "r"((uint32_t)(addr)), "r"((uint32_t)(cnt)) : "memory")
#define MBARRIER_EXPECT_TX(addr, bytes) \
    asm volatile("mbarrier.arrive.expect_tx.shared.b64 _, [%0], %1;" :: "r"((uint32_t)(addr)), "r"((uint32_t)(bytes)) : "memory")

__device__ __forceinline__ void mbar_wait(uint32_t mbar, uint32_t phase) {
    asm volatile(
        "{\n\t"
        ".reg .pred P;\n\t"
        "LAB_WAIT%=:\n\t"
        "mbarrier.try_wait.parity.acquire.cta.shared::cta.b64 P, [%0], %1, 0x989680;\n\t"
        "@!P bra LAB_WAIT%=;\n\t"
        "}"
        :: "r"(mbar), "r"(phase) : "memory");
}
__device__ __forceinline__ void bulk_g2s(uint32_t dst, const void* src, uint32_t bytes, uint32_t mbar) {
    asm volatile(
        "cp.async.bulk.shared::cluster.global.mbarrier::complete_tx::bytes [%0], [%1], %2, [%3];"
        :: "r"(dst), "l"(src), "r"(bytes), "r"(mbar) : "memory");
}

// block-internal swizzle: rows of 128B (64 halfs), 16B chunk c16 XOR row.
__device__ __forceinline__ uint32_t swz(uint32_t r, uint32_t c16) {
    return r * 128u + (((c16 ^ (r & 7u)) & 7u) << 4);
}

__device__ __forceinline__ void ldsm_x4(uint32_t* r, uint32_t addr) {
    asm volatile("ldmatrix.sync.aligned.m8n8.x4.shared.b16 {%0,%1,%2,%3}, [%4];"
                 : "=r"(r[0]), "=r"(r[1]), "=r"(r[2]), "=r"(r[3]) : "r"(addr));
}
__device__ __forceinline__ void mma16816(float* c, const uint32_t* a, uint32_t b0, uint32_t b1) {
    asm volatile(
        "mma.sync.aligned.m16n8k16.row.col.f32.f16.f16.f32 "
        "{%0,%1,%2,%3}, {%4,%5,%6,%7}, {%8,%9}, {%0,%1,%2,%3};"
        : "+f"(c[0]), "+f"(c[1]), "+f"(c[2]), "+f"(c[3])
        : "r"(a[0]), "r"(a[1]), "r"(a[2]), "r"(a[3]), "r"(b0), "r"(b1));
}

__device__ __forceinline__ float sigm_f(float x) { return __fdividef(1.0f, 1.0f + __expf(-x)); }
__device__ __forceinline__ float tanh_f(float x) { return __fdividef(2.0f, 1.0f + __expf(-2.0f * x)) - 1.0f; }

// ---------------------------------------------------------------- merged pack (unchanged from R9)
__global__ void __launch_bounds__(256) pack_all(const float* __restrict__ x,
                                                const float* __restrict__ h,
                                                const float* __restrict__ W,
                                                const float* __restrict__ V) {
    if (blockIdx.x < 1024) {
        const int kc = (int)blockIdx.x & 31;
        unsigned char* dst = g_Apack + ((size_t)blockIdx.x << 14);
        const int m0 = ((int)blockIdx.x >> 5) * 128, k0 = kc * 64;
        const float* srcb = (k0 < 1024) ? (x + (size_t)m0 * 1024 + k0)
                                        : (h + (size_t)m0 * 1024 + (k0 - 1024));
#pragma unroll
        for (int i = 0; i < 4; i++) {
            int idx = (int)threadIdx.x + i * 256;    // 0..1023 16B chunks
            uint32_t r = (uint32_t)(idx >> 3);
            uint32_t c16 = (uint32_t)(idx & 7);
            const float* s = srcb + (size_t)r * 1024 + c16 * 8;
            float4 v0 = *reinterpret_cast<const float4*>(s);
            float4 v1 = *reinterpret_cast<const float4*>(s + 4);
            __half2 h0 = __floats2half2_rn(v0.x, v0.y);
            __half2 h1 = __floats2half2_rn(v0.z, v0.w);
            __half2 h2 = __floats2half2_rn(v1.x, v1.y);
            __half2 h3 = __floats2half2_rn(v1.z, v1.w);
            uint4 pk = make_uint4(*reinterpret_cast<uint32_t*>(&h0), *reinterpret_cast<uint32_t*>(&h1),
                                  *reinterpret_cast<uint32_t*>(&h2), *reinterpret_cast<uint32_t*>(&h3));
            *reinterpret_cast<uint4*>(dst + swz(r, c16)) = pk;
        }
    } else {
        __shared__ float buf[32][33];
        const int idx0 = (int)blockIdx.x - 1024;
        const int nblk = idx0 & 127;   // orig n / 32
        const int kblk = idx0 >> 7;    // k / 32
        const int n0 = nblk * 32, k0 = kblk * 32;
        const float* src = (k0 < 1024) ? (W + (size_t)k0 * 4096 + n0)
                                       : (V + (size_t)(k0 - 1024) * 4096 + n0);
        for (int idx = threadIdx.x; idx < 1024; idx += 256) {
            int kl = idx >> 5, nl = idx & 31;
            buf[kl][nl] = src[(size_t)kl * 4096 + nl];
        }
        __syncthreads();
        const int kchunk = kblk >> 1;
        const int kbase = (kblk & 1) * 32;
        for (int idx = threadIdx.x; idx < 512; idx += 256) {
            int nl = idx >> 4;
            int kp = (idx & 15) * 2;
            int norig = n0 + nl;
            int g = norig >> 10;
            int rem = norig & 1023;
            int np = ((rem >> 5) << 7) + (((rem >> 3) & 3) << 5) + (g << 3) + (rem & 7);
            int nt = np >> 7;
            uint32_t r = (uint32_t)(np & 127);
            uint32_t kl = (uint32_t)(kbase + kp);
            __half2 hv = __floats2half2_rn(buf[kp][nl], buf[kp + 1][nl]);
            unsigned char* dst = g_Bpack + (((size_t)nt * NT_K + kchunk) << 14);
            *reinterpret_cast<uint32_t*>(dst + swz(r, kl >> 3) + (kl & 7) * 2) =
                *reinterpret_cast<uint32_t*>(&hv);
        }
    }
}

// ---------------------------------------------------------------- main GEMM + epilogue
// grid (32 j-blocks, 32 m-blocks), 256 threads = 8 warps (wm 0..1 x wn 0..3),
// warp tile 64x32 (4 m16 x 4 n8 = gates). 3-stage TMA pipeline, 2 CTAs/SM.
__global__ void __launch_bounds__(256, 2) lstm_main(const float* __restrict__ c_in,
                                                    const float* __restrict__ bias,
                                                    float* __restrict__ out) {
    extern __shared__ __align__(1024) unsigned char smem[];
    const uint32_t sb = smem_u32(smem);
    const int tid  = threadIdx.x;
    const int lane = tid & 31;
    const int warp = tid >> 5;
    const int wm = warp >> 2;       // 0..1 (64 rows)
    const int wn = warp & 3;        // 0..3 (32 B'cols = 4 gates x 8 j)
    const int bx = blockIdx.x;
    const int by = blockIdx.y;

    const uint32_t BAR = sb + SMEM_MAIN;   // full[0..2]
    if (tid == 0) {
        MBARRIER_INIT(BAR, 1);
        MBARRIER_INIT(BAR + 8, 1);
        MBARRIER_INIT(BAR + 16, 1);
    }
    __syncthreads();

    const unsigned char* Ab = g_Apack + ((size_t)by * NT_K << 14);
    const unsigned char* Bb = g_Bpack + ((size_t)bx * NT_K << 14);

    auto issue = [&](int it) {
        const uint32_t s3 = (uint32_t)(it % NSTAGE);
        const uint32_t bar = BAR + s3 * 8;
        const uint32_t dst = sb + s3 * STAGE_BYTES;
        MBARRIER_EXPECT_TX(bar, STAGE_BYTES);
        bulk_g2s(dst, Ab + ((size_t)it << 14), TILE_BYTES, bar);
        bulk_g2s(dst + TILE_BYTES, Bb + ((size_t)it << 14), TILE_BYTES, bar);
    };

    if (tid == 0) { issue(0); issue(1); }

    // per-warp ldmatrix bases (csel folded); per-ldsm cost = 1 XOR + 1 IADD
    const uint32_t rlo  = (uint32_t)(lane & 15);
    const uint32_t csel = (uint32_t)(lane >> 4);
    uint32_t pA[4], pB[2];
#pragma unroll
    for (int mt = 0; mt < 4; ++mt) {
        uint32_t rowa = (uint32_t)(wm * 64 + mt * 16) + rlo;
        pA[mt] = sb + rowa * 128u + ((((rowa & 7u) ^ csel) & 7u) << 4);
    }
#pragma unroll
    for (int gp = 0; gp < 2; ++gp) {
        uint32_t rowb = (uint32_t)(wn * 32 + gp * 16) + rlo;
        pB[gp] = sb + TILE_BYTES + rowb * 128u + ((((rowb & 7u) ^ csel) & 7u) << 4);
    }

    float acc[4][4][4];
#pragma unroll
    for (int i = 0; i < 4; i++)
#pragma unroll
        for (int j = 0; j < 4; j++)
#pragma unroll
            for (int q = 0; q < 4; q++) acc[i][j][q] = 0.0f;

    const int NIT = NT_K;  // 32
    int phase = 0;
    for (int it = 0; it < NIT; ++it) {
        const uint32_t s = (uint32_t)(it % NSTAGE);
        mbar_wait(BAR + s * 8, (uint32_t)phase);
        if (s == NSTAGE - 1) phase ^= 1;
        __syncthreads();                       // all warps done with stage it-1's buffer
        if (tid == 0 && it + 2 < NIT) issue(it + 2);

        const uint32_t so = s * STAGE_BYTES;
#pragma unroll
        for (int k16 = 0; k16 < 4; ++k16) {
            const uint32_t kx = (uint32_t)(k16 << 5) + so;
            uint32_t a[4][4];
#pragma unroll
            for (int mt = 0; mt < 4; ++mt) ldsm_x4(a[mt], (pA[mt] + so) ^ (uint32_t)(k16 << 5));
#pragma unroll
            for (int gp = 0; gp < 2; ++gp) {
                uint32_t r4[4];
                ldsm_x4(r4, (pB[gp] + so) ^ (uint32_t)(k16 << 5));
#pragma unroll
                for (int mt = 0; mt < 4; ++mt) {
                    mma16816(acc[mt][2 * gp + 0], a[mt], r4[0], r4[2]);
                    mma16816(acc[mt][2 * gp + 1], a[mt], r4[1], r4[3]);
                }
            }
        }
    }

    // ---- epilogue (fully in-register: nt == gate)
    const int jg = bx * 32 + wn * 8 + 2 * (lane & 3);
    float bi[4][2];
#pragma unroll
    for (int g = 0; g < 4; ++g) {
        bi[g][0] = bias[g * 1024 + jg];
        bi[g][1] = bias[g * 1024 + jg + 1];
    }
#pragma unroll
    for (int mt = 0; mt < 4; ++mt) {
#pragma unroll
        for (int hr = 0; hr < 2; ++hr) {
            int m = by * 128 + wm * 64 + mt * 16 + (lane >> 2) + hr * 8;
            const float2 cv = *reinterpret_cast<const float2*>(c_in + (size_t)m * 1024 + jg);
            float hv[2], co[2];
#pragma unroll
            for (int q = 0; q < 2; ++q) {
                float ai = acc[mt][0][hr * 2 + q] + bi[0][q];
                float af = acc[mt][1][hr * 2 + q] + bi[1][q];
                float ao = acc[mt][2][hr * 2 + q] + bi[2][q];
                float ag = acc[mt][3][hr * 2 + q] + bi[3][q];
                float iv = sigm_f(ai);
                float fv = sigm_f(af);
                float ov = sigm_f(ao);
                float gv = tanh_f(ag);
                float cc = (q == 0) ? cv.x : cv.y;
                float c2 = fmaf(iv, gv, fv * cc);
                co[q] = c2;
                hv[q] = ov * tanh_f(c2);
            }
            *reinterpret_cast<float2*>(out + (size_t)m * 1024 + jg) = make_float2(hv[0], hv[1]);
            *reinterpret_cast<float2*>(out + (size_t)BATCH * 1024 + (size_t)m * 1024 + jg) =
                make_float2(co[0], co[1]);
        }
    }
}

// ---------------------------------------------------------------- launch
extern "C" void kernel_launch(void* const* d_in, const int* in_sizes, int n_in,
                              void* d_out, int out_size) {
    (void)in_sizes; (void)n_in; (void)out_size;
    const float* x = (const float*)d_in[0];
    const float* h = (const float*)d_in[1];
    const float* c = (const float*)d_in[2];
    const float* W = (const float*)d_in[3];
    const float* V = (const float*)d_in[4];
    const float* b = (const float*)d_in[5];
    float* out = (float*)d_out;

    cudaFuncSetAttribute(lstm_main, cudaFuncAttributeMaxDynamicSharedMemorySize, SMEM_TOTAL);

    pack_all<<<9216, 256>>>(x, h, W, V);
    lstm_main<<<dim3(32, 32), 256, SMEM_TOTAL>>>(c, b, out);
}

// round 12
// speedup vs baseline: 1.1333x; 1.0076x over previous
#include <cuda_runtime.h>
#include <cuda_fp16.h>
#include <cstdint>

// ============================================================================
// LSTMCell on sm_100 (baseline PTX). mma.sync.m16n8k16 f16/f32.
// R10 -> R11/R12: kill the per-iteration __syncthreads lockstep. Full/empty
// mbarrier producer-consumer pipeline with per-warp progress; warps skew so
// LDSM of one warp overlaps HMMA of another (the sync was re-phasing all 8
// warps every iter, draining tensor during ldsm bursts and L1 during mma
// bursts -> both pipes stuck ~60%). Tiles/packs unchanged from R10.
// (R12 = identical resubmit of R11: infra failed before compile/run.)
// ============================================================================

#define BATCH 4096
#define KTOT  2048
#define NT_K 32                    // 2048/64 k-chunks
#define TILE_BYTES 16384           // 128 x 64 halfs, swizzled block
#define STAGE_BYTES 32768          // A block + B block
#define NSTAGE 3
#define SMEM_MAIN  (NSTAGE * STAGE_BYTES)
#define SMEM_TOTAL (SMEM_MAIN + 128)

__device__ __align__(1024) unsigned char g_Apack[(size_t)32 * NT_K * TILE_BYTES];  // 16 MB
__device__ __align__(1024) unsigned char g_Bpack[(size_t)32 * NT_K * TILE_BYTES];  // 16 MB

// ---------------------------------------------------------------- helpers
__device__ __forceinline__ uint32_t smem_u32(const void* p) {
    uint32_t a;
    asm("{ .reg .u64 t; cvta.to.shared.u64 t, %1; cvt.u32.u64 %0, t; }" : "=r"(a) : "l"(p));
    return a;
}
#define MBARRIER_INIT(addr, cnt) \
    asm volatile("mbarrier.init.shared.b64 [%0], %1;" :: "r"((uint32_t)(addr)), "r"((uint32_t)(cnt)) : "memory")
#define MBARRIER_EXPECT_TX(addr, bytes) \
    asm volatile("mbarrier.arrive.expect_tx.shared.b64 _, [%0], %1;" :: "r"((uint32_t)(addr)), "r"((uint32_t)(bytes)) : "memory")
#define MBARRIER_ARRIVE(addr) \
    asm volatile("mbarrier.arrive.shared.b64 _, [%0];" :: "r"((uint32_t)(addr)) : "memory")

__device__ __forceinline__ void mbar_wait(uint32_t mbar, uint32_t phase) {
    asm volatile(
        "{\n\t"
        ".reg .pred P;\n\t"
        "LAB_WAIT%=:\n\t"
        "mbarrier.try_wait.parity.acquire.cta.shared::cta.b64 P, [%0], %1, 0x989680;\n\t"
        "@!P bra LAB_WAIT%=;\n\t"
        "}"
        :: "r"(mbar), "r"(phase) : "memory");
}
__device__ __forceinline__ void bulk_g2s(uint32_t dst, const void* src, uint32_t bytes, uint32_t mbar) {
    asm volatile(
        "cp.async.bulk.shared::cluster.global.mbarrier::complete_tx::bytes [%0], [%1], %2, [%3];"
        :: "r"(dst), "l"(src), "r"(bytes), "r"(mbar) : "memory");
}

// block-internal swizzle: rows of 128B (64 halfs), 16B chunk c16 XOR row.
__device__ __forceinline__ uint32_t swz(uint32_t r, uint32_t c16) {
    return r * 128u + (((c16 ^ (r & 7u)) & 7u) << 4);
}

__device__ __forceinline__ void ldsm_x4(uint32_t* r, uint32_t addr) {
    asm volatile("ldmatrix.sync.aligned.m8n8.x4.shared.b16 {%0,%1,%2,%3}, [%4];"
                 : "=r"(r[0]), "=r"(r[1]), "=r"(r[2]), "=r"(r[3]) : "r"(addr));
}
__device__ __forceinline__ void mma16816(float* c, const uint32_t* a, uint32_t b0, uint32_t b1) {
    asm volatile(
        "mma.sync.aligned.m16n8k16.row.col.f32.f16.f16.f32 "
        "{%0,%1,%2,%3}, {%4,%5,%6,%7}, {%8,%9}, {%0,%1,%2,%3};"
        : "+f"(c[0]), "+f"(c[1]), "+f"(c[2]), "+f"(c[3])
        : "r"(a[0]), "r"(a[1]), "r"(a[2]), "r"(a[3]), "r"(b0), "r"(b1));
}

__device__ __forceinline__ float sigm_f(float x) { return __fdividef(1.0f, 1.0f + __expf(-x)); }
__device__ __forceinline__ float tanh_f(float x) { return __fdividef(2.0f, 1.0f + __expf(-2.0f * x)) - 1.0f; }

// ---------------------------------------------------------------- merged pack (unchanged)
__global__ void __launch_bounds__(256) pack_all(const float* __restrict__ x,
                                                const float* __restrict__ h,
                                                const float* __restrict__ W,
                                                const float* __restrict__ V) {
    if (blockIdx.x < 1024) {
        const int kc = (int)blockIdx.x & 31;
        unsigned char* dst = g_Apack + ((size_t)blockIdx.x << 14);
        const int m0 = ((int)blockIdx.x >> 5) * 128, k0 = kc * 64;
        const float* srcb = (k0 < 1024) ? (x + (size_t)m0 * 1024 + k0)
                                        : (h + (size_t)m0 * 1024 + (k0 - 1024));
#pragma unroll
        for (int i = 0; i < 4; i++) {
            int idx = (int)threadIdx.x + i * 256;    // 0..1023 16B chunks
            uint32_t r = (uint32_t)(idx >> 3);
            uint32_t c16 = (uint32_t)(idx & 7);
            const float* s = srcb + (size_t)r * 1024 + c16 * 8;
            float4 v0 = *reinterpret_cast<const float4*>(s);
            float4 v1 = *reinterpret_cast<const float4*>(s + 4);
            __half2 h0 = __floats2half2_rn(v0.x, v0.y);
            __half2 h1 = __floats2half2_rn(v0.z, v0.w);
            __half2 h2 = __floats2half2_rn(v1.x, v1.y);
            __half2 h3 = __floats2half2_rn(v1.z, v1.w);
            uint4 pk = make_uint4(*reinterpret_cast<uint32_t*>(&h0), *reinterpret_cast<uint32_t*>(&h1),
                                  *reinterpret_cast<uint32_t*>(&h2), *reinterpret_cast<uint32_t*>(&h3));
            *reinterpret_cast<uint4*>(dst + swz(r, c16)) = pk;
        }
    } else {
        __shared__ float buf[32][33];
        const int idx0 = (int)blockIdx.x - 1024;
        const int nblk = idx0 & 127;   // orig n / 32
        const int kblk = idx0 >> 7;    // k / 32
        const int n0 = nblk * 32, k0 = kblk * 32;
        const float* src = (k0 < 1024) ? (W + (size_t)k0 * 4096 + n0)
                                       : (V + (size_t)(k0 - 1024) * 4096 + n0);
        for (int idx = threadIdx.x; idx < 1024; idx += 256) {
            int kl = idx >> 5, nl = idx & 31;
            buf[kl][nl] = src[(size_t)kl * 4096 + nl];
        }
        __syncthreads();
        const int kchunk = kblk >> 1;
        const int kbase = (kblk & 1) * 32;
        for (int idx = threadIdx.x; idx < 512; idx += 256) {
            int nl = idx >> 4;
            int kp = (idx & 15) * 2;
            int norig = n0 + nl;
            int g = norig >> 10;
            int rem = norig & 1023;
            int np = ((rem >> 5) << 7) + (((rem >> 3) & 3) << 5) + (g << 3) + (rem & 7);
            int nt = np >> 7;
            uint32_t r = (uint32_t)(np & 127);
            uint32_t kl = (uint32_t)(kbase + kp);
            __half2 hv = __floats2half2_rn(buf[kp][nl], buf[kp + 1][nl]);
            unsigned char* dst = g_Bpack + (((size_t)nt * NT_K + kchunk) << 14);
            *reinterpret_cast<uint32_t*>(dst + swz(r, kl >> 3) + (kl & 7) * 2) =
                *reinterpret_cast<uint32_t*>(&hv);
        }
    }
}

// ---------------------------------------------------------------- main GEMM + epilogue
// grid (32, 32), 256 threads = 8 warps (wm 0..1 x wn 0..3), warp tile 64x32
// (4 m16 x 4 n8 = gates). 3-stage TMA pipeline, full/empty mbarriers, no
// __syncthreads in the mainloop. 2 CTAs/SM.
__global__ void __launch_bounds__(256, 2) lstm_main(const float* __restrict__ c_in,
                                                    const float* __restrict__ bias,
                                                    float* __restrict__ out) {
    extern __shared__ __align__(1024) unsigned char smem[];
    const uint32_t sb = smem_u32(smem);
    const int tid  = threadIdx.x;
    const int lane = tid & 31;
    const int warp = tid >> 5;
    const int wm = warp >> 2;       // 0..1 (64 rows)
    const int wn = warp & 3;        // 0..3 (32 B'cols = 4 gates x 8 j)
    const int bx = blockIdx.x;
    const int by = blockIdx.y;

    const uint32_t FULLB  = sb + SMEM_MAIN;        // full[0..2] @ +0,8,16
    const uint32_t EMPTYB = sb + SMEM_MAIN + 24;   // empty[0..2] @ +0,8,16
    if (tid == 0) {
#pragma unroll
        for (int s = 0; s < NSTAGE; ++s) {
            MBARRIER_INIT(FULLB + s * 8, 1);       // tx-based
            MBARRIER_INIT(EMPTYB + s * 8, 8);      // one arrive per warp
        }
    }
    __syncthreads();

    const unsigned char* Ab = g_Apack + ((size_t)by * NT_K << 14);
    const unsigned char* Bb = g_Bpack + ((size_t)bx * NT_K << 14);

    auto issue = [&](int it) {
        const uint32_t s3 = (uint32_t)(it % NSTAGE);
        const uint32_t bar = FULLB + s3 * 8;
        const uint32_t dst = sb + s3 * STAGE_BYTES;
        MBARRIER_EXPECT_TX(bar, STAGE_BYTES);
        bulk_g2s(dst, Ab + ((size_t)it << 14), TILE_BYTES, bar);
        bulk_g2s(dst + TILE_BYTES, Bb + ((size_t)it << 14), TILE_BYTES, bar);
    };

    if (tid == 0) { issue(0); issue(1); }

    // per-warp ldmatrix bases (csel folded); per-ldsm cost = 1 IADD + 1 XOR
    const uint32_t rlo  = (uint32_t)(lane & 15);
    const uint32_t csel = (uint32_t)(lane >> 4);
    uint32_t pA[4], pB[2];
#pragma unroll
    for (int mt = 0; mt < 4; ++mt) {
        uint32_t rowa = (uint32_t)(wm * 64 + mt * 16) + rlo;
        pA[mt] = sb + rowa * 128u + ((((rowa & 7u) ^ csel) & 7u) << 4);
    }
#pragma unroll
    for (int gp = 0; gp < 2; ++gp) {
        uint32_t rowb = (uint32_t)(wn * 32 + gp * 16) + rlo;
        pB[gp] = sb + TILE_BYTES + rowb * 128u + ((((rowb & 7u) ^ csel) & 7u) << 4);
    }

    float acc[4][4][4];
#pragma unroll
    for (int i = 0; i < 4; i++)
#pragma unroll
        for (int j = 0; j < 4; j++)
#pragma unroll
            for (int q = 0; q < 4; q++) acc[i][j][q] = 0.0f;

    const int NIT = NT_K;  // 32
    for (int it = 0; it < NIT; ++it) {
        const uint32_t s = (uint32_t)(it % NSTAGE);

        // producer: re-issue into stage s2 once its previous consumers drained
        if (tid == 0 && it + 2 < NIT) {
            const int it2 = it + 2;
            const uint32_t s2 = (uint32_t)(it2 % NSTAGE);
            if (it2 >= NSTAGE)
                mbar_wait(EMPTYB + s2 * 8, (uint32_t)(((it2 / NSTAGE) - 1) & 1));
            issue(it2);
        }

        // consumer: per-warp wait for this stage's fill
        mbar_wait(FULLB + s * 8, (uint32_t)((it / NSTAGE) & 1));

        const uint32_t so = s * STAGE_BYTES;
#pragma unroll
        for (int k16 = 0; k16 < 4; ++k16) {
            const uint32_t kx = (uint32_t)(k16 << 5);
            uint32_t a[4][4];
#pragma unroll
            for (int mt = 0; mt < 4; ++mt) ldsm_x4(a[mt], (pA[mt] + so) ^ kx);
#pragma unroll
            for (int gp = 0; gp < 2; ++gp) {
                uint32_t r4[4];
                ldsm_x4(r4, (pB[gp] + so) ^ kx);
#pragma unroll
                for (int mt = 0; mt < 4; ++mt) {
                    mma16816(acc[mt][2 * gp + 0], a[mt], r4[0], r4[2]);
                    mma16816(acc[mt][2 * gp + 1], a[mt], r4[1], r4[3]);
                }
            }
        }

        // this warp is done with stage s (MMAs consumed the fragments)
        if (lane == 0) MBARRIER_ARRIVE(EMPTYB + s * 8);
    }

    // ---- epilogue (fully in-register: nt == gate)
    const int jg = bx * 32 + wn * 8 + 2 * (lane & 3);
    float bi[4][2];
#pragma unroll
    for (int g = 0; g < 4; ++g) {
        bi[g][0] = bias[g * 1024 + jg];
        bi[g][1] = bias[g * 1024 + jg + 1];
    }
#pragma unroll
    for (int mt = 0; mt < 4; ++mt) {
#pragma unroll
        for (int hr = 0; hr < 2; ++hr) {
            int m = by * 128 + wm * 64 + mt * 16 + (lane >> 2) + hr * 8;
            const float2 cv = *reinterpret_cast<const float2*>(c_in + (size_t)m * 1024 + jg);
            float hv[2], co[2];
#pragma unroll
            for (int q = 0; q < 2; ++q) {
                float ai = acc[mt][0][hr * 2 + q] + bi[0][q];
                float af = acc[mt][1][hr * 2 + q] + bi[1][q];
                float ao = acc[mt][2][hr * 2 + q] + bi[2][q];
                float ag = acc[mt][3][hr * 2 + q] + bi[3][q];
                float iv = sigm_f(ai);
                float fv = sigm_f(af);
                float ov = sigm_f(ao);
                float gv = tanh_f(ag);
                float cc = (q == 0) ? cv.x : cv.y;
                float c2 = fmaf(iv, gv, fv * cc);
                co[q] = c2;
                hv[q] = ov * tanh_f(c2);
            }
            *reinterpret_cast<float2*>(out + (size_t)m * 1024 + jg) = make_float2(hv[0], hv[1]);
            *reinterpret_cast<float2*>(out + (size_t)BATCH * 1024 + (size_t)m * 1024 + jg) =
                make_float2(co[0], co[1]);
        }
    }
}

// ---------------------------------------------------------------- launch
extern "C" void kernel_launch(void* const* d_in, const int* in_sizes, int n_in,
                              void* d_out, int out_size) {
    (void)in_sizes; (void)n_in; (void)out_size;
    const float* x = (const float*)d_in[0];
    const float* h = (const float*)d_in[1];
    const float* c = (const float*)d_in[2];
    const float* W = (const float*)d_in[3];
    const float* V = (const float*)d_in[4];
    const float* b = (const float*)d_in[5];
    float* out = (float*)d_out;

    cudaFuncSetAttribute(lstm_main, cudaFuncAttributeMaxDynamicSharedMemorySize, SMEM_TOTAL);

    pack_all<<<9216, 256>>>(x, h, W, V);
    lstm_main<<<dim3(32, 32), 256, SMEM_TOTAL>>>(c, b, out);
}